// round 1
// baseline (speedup 1.0000x reference)
#include <cuda_runtime.h>
#include <math.h>
#include <stdint.h>

#define NN   50000
#define EE   800000
#define BB   128
#define KEXP 4
#define EPSF 1e-15f

// ---------------- scratch (device globals; no allocs allowed) ----------------
__device__ float g_dinv[NN];
__device__ int   g_degcnt[NN];
__device__ int   g_off[NN + 1];
__device__ int   g_cursor[NN];
__device__ int   g_adj[EE];
__device__ float g_xm[NN * 128];
__device__ float g_mx[NN * 128];   // also reused for gate m1 [N,32] and m2 [N,128]
__device__ float g_t [NN * 128];
__device__ float g_g1[NN * 32];
__device__ float g_feat[BB * 512];
__device__ float g_hgate[BB * 128];
__device__ float g_biaspt[128];
__device__ float g_bp2;

// ---------------- math helpers ----------------
__device__ __forceinline__ float tan_k(float x, float k) {
    if (k > 0.f) { float sk = sqrtf(k);  return tanf(x * sk) / sk; }
    if (k < 0.f) { float sk = sqrtf(-k); return tanhf(x * sk) / sk; }
    return x;
}
__device__ __forceinline__ float artan_k(float x, float k) {
    if (k > 0.f) { float sk = sqrtf(k);  return atanf(x * sk) / sk; }
    if (k < 0.f) {
        float sk = sqrtf(-k);
        float z = fminf(fmaxf(x * sk, -1.0f + 1e-7f), 1.0f - 1e-7f);
        return atanhf(z) / sk;
    }
    return x;
}
__device__ __forceinline__ float warp_sum(float v) {
#pragma unroll
    for (int o = 16; o; o >>= 1) v += __shfl_xor_sync(0xffffffffu, v, o);
    return v;
}
// project (Poincare clip) for a lane-distributed 4-float vector (warp holds 128 dims)
__device__ __forceinline__ void project_w(float* v, float k) {
    if (k >= 0.f) return;
    float s2 = v[0]*v[0] + v[1]*v[1] + v[2]*v[2] + v[3]*v[3];
    float n = fmaxf(sqrtf(warp_sum(s2)), EPSF);
    float maxn = (1.0f - 1e-5f) * rsqrtf(-k);
    if (n > maxn) {
        float f = maxn / n;
#pragma unroll
        for (int c = 0; c < 4; c++) v[c] *= f;
    }
}
__device__ __forceinline__ void expmap0_w(float* v, float k) {
    float s2 = v[0]*v[0] + v[1]*v[1] + v[2]*v[2] + v[3]*v[3];
    float n = fmaxf(sqrtf(warp_sum(s2)), EPSF);
    float s = tan_k(n, k) / n;
#pragma unroll
    for (int c = 0; c < 4; c++) v[c] *= s;
    project_w(v, k);
}
__device__ __forceinline__ void logmap0_w(float* v, float k) {
    float s2 = v[0]*v[0] + v[1]*v[1] + v[2]*v[2] + v[3]*v[3];
    float n = fmaxf(sqrtf(warp_sum(s2)), EPSF);
    float s = artan_k(n, k) / n;
#pragma unroll
    for (int c = 0; c < 4; c++) v[c] *= s;
}
__device__ __forceinline__ int lower_bound_batch(const int* __restrict__ b, int val) {
    int lo = 0, hi = NN;
    while (lo < hi) { int mid = (lo + hi) >> 1; if (b[mid] < val) lo = mid + 1; else hi = mid; }
    return lo;
}
// 128-thread block reduce
__device__ __forceinline__ float bred128(float v, float* sh) {
    v = warp_sum(v);
    int w = threadIdx.x >> 5;
    if ((threadIdx.x & 31) == 0) sh[w] = v;
    __syncthreads();
    float r = sh[0] + sh[1] + sh[2] + sh[3];
    __syncthreads();
    return r;
}

// ---------------- graph prep ----------------
__global__ void k_init() {
    int i = blockIdx.x * blockDim.x + threadIdx.x;
    if (i < NN) { g_degcnt[i] = 0; g_cursor[i] = 0; }
}
__global__ void k_deg(const int* __restrict__ col) {
    int e = blockIdx.x * blockDim.x + threadIdx.x;
    if (e < EE) atomicAdd(&g_degcnt[col[e]], 1);
}
__global__ void k_dinv() {
    int i = blockIdx.x * blockDim.x + threadIdx.x;
    if (i < NN) g_dinv[i] = rsqrtf((float)(g_degcnt[i] + 1));
}
__global__ void k_scan() {  // exclusive scan of g_degcnt -> g_off (single block, 1024 thr)
    __shared__ int s[1024];
    int t = threadIdx.x;
    int run = 0;
    for (int base = 0; base < NN; base += 1024) {
        int v = (base + t < NN) ? g_degcnt[base + t] : 0;
        s[t] = v;
        __syncthreads();
#pragma unroll
        for (int o = 1; o < 1024; o <<= 1) {
            int x = (t >= o) ? s[t - o] : 0;
            __syncthreads();
            s[t] += x;
            __syncthreads();
        }
        int incl = s[t];
        if (base + t < NN) g_off[base + t] = run + incl - v;
        int tot = s[1023];
        __syncthreads();
        run += tot;
    }
    if (t == 0) g_off[NN] = run;
}
__global__ void k_adj(const int* __restrict__ row, const int* __restrict__ col) {
    int e = blockIdx.x * blockDim.x + threadIdx.x;
    if (e < EE) {
        int d = col[e];
        int p = g_off[d] + atomicAdd(&g_cursor[d], 1);
        g_adj[p] = row[e];
    }
}

// ---------------- expert point kernels (warp per node) ----------------
__global__ void k_expmap_init(const float* __restrict__ x, float k) {
    int node = blockIdx.x * 8 + (threadIdx.x >> 5);
    if (node >= NN) return;
    int lane = threadIdx.x & 31;
    float v[4];
#pragma unroll
    for (int c = 0; c < 4; c++) v[c] = x[node * 128 + c * 32 + lane];
    expmap0_w(v, k);
#pragma unroll
    for (int c = 0; c < 4; c++) g_xm[node * 128 + c * 32 + lane] = v[c];
}

__global__ void k_bias(const float* __restrict__ b, float k) {
    __shared__ float sh[4];
    int t = threadIdx.x;  // 128 threads
    float v = b[t];
    float n2 = bred128(v * v, sh);
    float n = fmaxf(sqrtf(n2), EPSF);
    float p = (tan_k(n, k) / n) * v;
    if (k < 0.f) {
        float p2 = bred128(p * p, sh);
        float pn = fmaxf(sqrtf(p2), EPSF);
        float maxn = (1.0f - 1e-5f) * rsqrtf(-k);
        if (pn > maxn) p *= maxn / pn;
    }
    float p2f = bred128(p * p, sh);
    g_biaspt[t] = p;
    if (t == 0) g_bp2 = p2f;
}

// mobius_matvec tail + mobius_add(bias) + logmap0  :  g_xm,g_mx -> g_t
__global__ void k_point(float k) {
    int node = blockIdx.x * 8 + (threadIdx.x >> 5);
    if (node >= NN) return;
    int lane = threadIdx.x & 31;
    const float* xm = g_xm + node * 128;
    const float* mx = g_mx + node * 128;
    float xv[4], mv[4], h[4];
#pragma unroll
    for (int c = 0; c < 4; c++) { xv[c] = xm[c * 32 + lane]; mv[c] = mx[c * 32 + lane]; }
    if (k == 0.f) {
#pragma unroll
        for (int c = 0; c < 4; c++) h[c] = mv[c];
    } else {
        float xn2 = 0.f, mn2 = 0.f, asum = 0.f;
#pragma unroll
        for (int c = 0; c < 4; c++) { xn2 += xv[c]*xv[c]; mn2 += mv[c]*mv[c]; asum += fabsf(mv[c]); }
        xn2 = warp_sum(xn2); mn2 = warp_sum(mn2); asum = warp_sum(asum);
        float xn  = fmaxf(sqrtf(xn2), EPSF);
        float mxn = fmaxf(sqrtf(mn2), EPSF);
        float s = tan_k(mxn / xn * artan_k(xn, k), k) / mxn;
#pragma unroll
        for (int c = 0; c < 4; c++) h[c] = (asum == 0.f) ? 0.f : s * mv[c];
        project_w(h, k);
    }
    // mobius_add(h, bias_pt)
    float bp[4];
#pragma unroll
    for (int c = 0; c < 4; c++) bp[c] = g_biaspt[c * 32 + lane];
    float bp2 = g_bp2;
    float h2s = 0.f, xys = 0.f;
#pragma unroll
    for (int c = 0; c < 4; c++) { h2s += h[c]*h[c]; xys += h[c]*bp[c]; }
    float h2 = warp_sum(h2s);
    float xy = warp_sum(xys);
    float num_h = 1.f - 2.f*k*xy - k*bp2;
    float num_b = 1.f + k*h2;
    float den = fmaxf(1.f - 2.f*k*xy + k*k*h2*bp2, 1e-15f);
    float a[4];
#pragma unroll
    for (int c = 0; c < 4; c++) a[c] = (num_h*h[c] + num_b*bp[c]) / den;
    project_w(a, k);
    logmap0_w(a, k);
#pragma unroll
    for (int c = 0; c < 4; c++) g_t[node * 128 + c * 32 + lane] = a[c];
}

// gather-aggregate over CSR + expmap0 : g_t -> g_xm
__global__ void k_aggexp(float k) {
    int d = blockIdx.x * 8 + (threadIdx.x >> 5);
    if (d >= NN) return;
    int lane = threadIdx.x & 31;
    float dd = g_dinv[d];
    float sw = dd * dd;
    float acc[4];
#pragma unroll
    for (int c = 0; c < 4; c++) acc[c] = sw * g_t[d * 128 + c * 32 + lane];
    int p0 = g_off[d], p1 = g_off[d + 1];
    for (int p = p0; p < p1; p += 32) {
        int cnt = min(32, p1 - p);
        int sv = 0; float wv = 0.f;
        if (p + lane < p1) { sv = g_adj[p + lane]; wv = dd * g_dinv[sv]; }
        for (int q = 0; q < cnt; q++) {
            int   s = __shfl_sync(0xffffffffu, sv, q);
            float w = __shfl_sync(0xffffffffu, wv, q);
            const float* ts = g_t + s * 128;
#pragma unroll
            for (int c = 0; c < 4; c++) acc[c] += w * ts[c * 32 + lane];
        }
    }
    expmap0_w(acc, k);
#pragma unroll
    for (int c = 0; c < 4; c++) g_xm[d * 128 + c * 32 + lane] = acc[c];
}

__global__ void k_logmap(float k) {  // g_xm -> g_t
    int node = blockIdx.x * 8 + (threadIdx.x >> 5);
    if (node >= NN) return;
    int lane = threadIdx.x & 31;
    float v[4];
#pragma unroll
    for (int c = 0; c < 4; c++) v[c] = g_xm[node * 128 + c * 32 + lane];
    logmap0_w(v, k);
#pragma unroll
    for (int c = 0; c < 4; c++) g_t[node * 128 + c * 32 + lane] = v[c];
}

// ---------------- GEMM: C[N,128] = A[N,KD] * W[128,KD]^T  (A selected by flag) ----------------
template<int KD>
__global__ void gemm(const float* __restrict__ W, int srcSel, int n) {
    const float* __restrict__ A = (srcSel == 0) ? g_xm : g_g1;
    __shared__ __align__(16) float As[32][132];
    __shared__ __align__(16) float Bs[32][132];
    int tid = threadIdx.x;              // 256
    int tx = tid & 15, ty = tid >> 4;   // 16x16
    int node0 = blockIdx.x * 128;
    float acc[8][8];
#pragma unroll
    for (int m = 0; m < 8; m++)
#pragma unroll
        for (int nn2 = 0; nn2 < 8; nn2++) acc[m][nn2] = 0.f;

    for (int k0 = 0; k0 < KD; k0 += 32) {
#pragma unroll
        for (int r = 0; r < 4; r++) {
            int m  = (tid >> 3) + r * 32;
            int kk = (tid & 7) * 4;
            float4 va = make_float4(0.f, 0.f, 0.f, 0.f);
            if (node0 + m < n)
                va = *(const float4*)(A + (size_t)(node0 + m) * KD + k0 + kk);
            As[kk + 0][m] = va.x; As[kk + 1][m] = va.y; As[kk + 2][m] = va.z; As[kk + 3][m] = va.w;
            float4 vb = *(const float4*)(W + (size_t)m * KD + k0 + kk);
            Bs[kk + 0][m] = vb.x; Bs[kk + 1][m] = vb.y; Bs[kk + 2][m] = vb.z; Bs[kk + 3][m] = vb.w;
        }
        __syncthreads();
#pragma unroll
        for (int kk = 0; kk < 32; kk++) {
            float4 a0 = *(const float4*)&As[kk][ty * 4];
            float4 a1 = *(const float4*)&As[kk][64 + ty * 4];
            float4 b0 = *(const float4*)&Bs[kk][tx * 4];
            float4 b1 = *(const float4*)&Bs[kk][64 + tx * 4];
            float a[8] = {a0.x, a0.y, a0.z, a0.w, a1.x, a1.y, a1.z, a1.w};
            float b[8] = {b0.x, b0.y, b0.z, b0.w, b1.x, b1.y, b1.z, b1.w};
#pragma unroll
            for (int m = 0; m < 8; m++)
#pragma unroll
                for (int nn2 = 0; nn2 < 8; nn2++) acc[m][nn2] = fmaf(a[m], b[nn2], acc[m][nn2]);
        }
        __syncthreads();
    }
#pragma unroll
    for (int m = 0; m < 8; m++) {
        int row = node0 + ((m < 4) ? (ty * 4 + m) : (64 + ty * 4 + m - 4));
        if (row < n) {
            float4 o0 = make_float4(acc[m][0], acc[m][1], acc[m][2], acc[m][3]);
            float4 o1 = make_float4(acc[m][4], acc[m][5], acc[m][6], acc[m][7]);
            *(float4*)(g_mx + (size_t)row * 128 + tx * 4)      = o0;
            *(float4*)(g_mx + (size_t)row * 128 + 64 + tx * 4) = o1;
        }
    }
}

// ---------------- gate ----------------
__global__ void k_gate1(const float* __restrict__ x, const float* __restrict__ gw1) {
    __shared__ float wT[128 * 33];
    int tid = threadIdx.x;
    for (int l = tid; l < 4096; l += 256) {
        int j = l >> 7, i = l & 127;
        wT[i * 33 + j] = gw1[l];
    }
    __syncthreads();
    int warp = tid >> 5, lane = tid & 31;
    for (int rep = 0; rep < 4; rep++) {
        int node = blockIdx.x * 32 + rep * 8 + warp;
        if (node < NN) {
            float xv[4];
#pragma unroll
            for (int c = 0; c < 4; c++) xv[c] = x[node * 128 + c * 32 + lane];
            float accv = 0.f;
#pragma unroll
            for (int i = 0; i < 128; i++) {
                float xi = __shfl_sync(0xffffffffu, xv[i >> 5], i & 31);
                accv = fmaf(xi, wT[i * 33 + lane], accv);
            }
            g_mx[node * 32 + lane] = accv;
        }
    }
}
__global__ void k_gagg1(const float* __restrict__ gb1) {  // 32-dim GCN agg + bias + relu
    int d = blockIdx.x * 8 + (threadIdx.x >> 5);
    if (d >= NN) return;
    int lane = threadIdx.x & 31;
    float dd = g_dinv[d];
    float acc = dd * dd * g_mx[d * 32 + lane];
    int p0 = g_off[d], p1 = g_off[d + 1];
    for (int p = p0; p < p1; p += 32) {
        int cnt = min(32, p1 - p);
        int sv = 0; float wv = 0.f;
        if (p + lane < p1) { sv = g_adj[p + lane]; wv = dd * g_dinv[sv]; }
        for (int q = 0; q < cnt; q++) {
            int   s = __shfl_sync(0xffffffffu, sv, q);
            float w = __shfl_sync(0xffffffffu, wv, q);
            acc += w * g_mx[s * 32 + lane];
        }
    }
    g_g1[d * 32 + lane] = fmaxf(acc + gb1[lane], 0.f);
}
__global__ void k_gagg2(const float* __restrict__ gb2) {  // 128-dim agg + bias + relu -> g_t
    int d = blockIdx.x * 8 + (threadIdx.x >> 5);
    if (d >= NN) return;
    int lane = threadIdx.x & 31;
    float dd = g_dinv[d];
    float sw = dd * dd;
    float acc[4];
#pragma unroll
    for (int c = 0; c < 4; c++) acc[c] = sw * g_mx[d * 128 + c * 32 + lane];
    int p0 = g_off[d], p1 = g_off[d + 1];
    for (int p = p0; p < p1; p += 32) {
        int cnt = min(32, p1 - p);
        int sv = 0; float wv = 0.f;
        if (p + lane < p1) { sv = g_adj[p + lane]; wv = dd * g_dinv[sv]; }
        for (int q = 0; q < cnt; q++) {
            int   s = __shfl_sync(0xffffffffu, sv, q);
            float w = __shfl_sync(0xffffffffu, wv, q);
            const float* ms = g_mx + s * 128;
#pragma unroll
            for (int c = 0; c < 4; c++) acc[c] += w * ms[c * 32 + lane];
        }
    }
#pragma unroll
    for (int c = 0; c < 4; c++)
        g_t[d * 128 + c * 32 + lane] = fmaxf(acc[c] + gb2[c * 32 + lane], 0.f);
}

// ---------------- pooling (deterministic via sorted batch) ----------------
__global__ void k_pool(int dstSel, int colOfs, const int* __restrict__ batch) {
    int b = blockIdx.x, j = threadIdx.x;  // 128 threads
    int s = lower_bound_batch(batch, b);
    int e = lower_bound_batch(batch, b + 1);
    float a0 = 0.f, a1 = 0.f, a2 = 0.f, a3 = 0.f;
    int nd = s;
    for (; nd + 4 <= e; nd += 4) {
        a0 += g_t[(size_t)(nd + 0) * 128 + j];
        a1 += g_t[(size_t)(nd + 1) * 128 + j];
        a2 += g_t[(size_t)(nd + 2) * 128 + j];
        a3 += g_t[(size_t)(nd + 3) * 128 + j];
    }
    for (; nd < e; ++nd) a0 += g_t[(size_t)nd * 128 + j];
    float sum = (a0 + a1) + (a2 + a3);
    if (dstSel == 0) g_feat[b * 512 + colOfs + j] = sum;
    else             g_hgate[b * 128 + j] = sum;
}

// ---------------- finalize: distance gate, softmax, output ----------------
__global__ void k_finalize(const float* __restrict__ gate_u, const float* __restrict__ tau_raw,
                           float* __restrict__ out, int out_size, const int* __restrict__ batch) {
    __shared__ float sh[4];
    int b = blockIdx.x, j = threadIdx.x;  // 128 threads
    int s = lower_bound_batch(batch, b);
    int e = lower_bound_batch(batch, b + 1);
    float c = fmaxf((float)(e - s), 1.0f);
    float hg = g_hgate[b * 128 + j] / c;
    float hn2 = bred128(hg * hg, sh);
    const float curv[4] = {-1.0f, 0.0f, 1.0f, -0.5f};
    float dv[4], tauv[4];
    for (int i = 0; i < 4; i++) {
        float k = curv[i];
        // zk = expmap0(hg, k)
        float zn = fmaxf(sqrtf(hn2), EPSF);
        float zk = (tan_k(zn, k) / zn) * hg;
        if (k < 0.f) {
            float z2 = bred128(zk * zk, sh);
            float n = fmaxf(sqrtf(z2), EPSF);
            float maxn = (1.0f - 1e-5f) * rsqrtf(-k);
            if (n > maxn) zk *= maxn / n;
        }
        // yk = expmap0(gate_u[i], k)
        float u = gate_u[i * 128 + j];
        float un2 = bred128(u * u, sh);
        float un = fmaxf(sqrtf(un2), EPSF);
        float yk = (tan_k(un, k) / un) * u;
        if (k < 0.f) {
            float y2p = bred128(yk * yk, sh);
            float n = fmaxf(sqrtf(y2p), EPSF);
            float maxn = (1.0f - 1e-5f) * rsqrtf(-k);
            if (n > maxn) yk *= maxn / n;
        }
        // mobius_add(-zk, yk, k)
        float xe = -zk;
        float x2 = bred128(xe * xe, sh);
        float y2 = bred128(yk * yk, sh);
        float xy = bred128(xe * yk, sh);
        float nh = 1.f - 2.f * k * xy - k * y2;
        float nb = 1.f + k * x2;
        float den = fmaxf(1.f - 2.f * k * xy + k * k * x2 * y2, 1e-15f);
        float m = (nh * xe + nb * yk) / den;
        if (k < 0.f) {
            float m2p = bred128(m * m, sh);
            float n = fmaxf(sqrtf(m2p), EPSF);
            float maxn = (1.0f - 1e-5f) * rsqrtf(-k);
            if (n > maxn) m *= maxn / n;
        }
        float m2 = bred128(m * m, sh);
        dv[i] = 2.0f * artan_k(fmaxf(sqrtf(m2), EPSF), k);
        float tr = tau_raw[i];
        float sp = (tr > 20.f) ? tr : log1pf(expf(tr));
        tauv[i] = fminf(fmaxf(sp + 0.05f, 0.05f), 10.0f);
    }
    // softmax(-d/tau)
    float l[4], mxl = -1e30f;
#pragma unroll
    for (int i = 0; i < 4; i++) { l[i] = -dv[i] / tauv[i]; mxl = fmaxf(mxl, l[i]); }
    float sum = 0.f;
#pragma unroll
    for (int i = 0; i < 4; i++) { l[i] = expf(l[i] - mxl); sum += l[i]; }
    float w[4];
#pragma unroll
    for (int i = 0; i < 4; i++) w[i] = l[i] / sum;
    // outputs: scaled [B,512] | weights [B,4] | dists [B,4] | tau [4]
#pragma unroll
    for (int i = 0; i < 4; i++) {
        int idx = b * 512 + i * 128 + j;
        out[idx] = (g_feat[idx] / c) * w[i];
    }
    if (out_size >= 66564) {
        if (j < 4) {
            out[65536 + b * 4 + j] = w[j];
            out[66048 + b * 4 + j] = dv[j];
            if (b == 0) out[66560 + j] = tauv[j];
        }
    }
}

// ---------------- launch ----------------
extern "C" void kernel_launch(void* const* d_in, const int* in_sizes, int n_in,
                              void* d_out, int out_size) {
    const float* x     = (const float*)d_in[0];
    const int*   ei    = (const int*)d_in[1];
    const int*   row   = ei;
    const int*   col   = ei + EE;
    const int*   batch = (const int*)d_in[2];
    const float* ew1   = (const float*)d_in[3];
    const float* eb1   = (const float*)d_in[4];
    const float* ew2   = (const float*)d_in[5];
    const float* eb2   = (const float*)d_in[6];
    const float* gw1   = (const float*)d_in[7];
    const float* gb1   = (const float*)d_in[8];
    const float* gw2   = (const float*)d_in[9];
    const float* gb2   = (const float*)d_in[10];
    const float* gu    = (const float*)d_in[11];
    const float* traw  = (const float*)d_in[12];
    float* out = (float*)d_out;

    const float curv[4] = {-1.0f, 0.0f, 1.0f, -0.5f};

    k_init<<<(NN + 255) / 256, 256>>>();
    k_deg<<<(EE + 255) / 256, 256>>>(col);
    k_dinv<<<(NN + 255) / 256, 256>>>();
    k_scan<<<1, 1024>>>();
    k_adj<<<(EE + 255) / 256, 256>>>(row, col);

    const int WG = (NN + 7) / 8;     // warp-per-node grids
    const int GG = (NN + 127) / 128; // gemm grids

    for (int i = 0; i < KEXP; i++) {
        float kv = curv[i];
        k_expmap_init<<<WG, 256>>>(x, kv);
        for (int L = 0; L < 2; L++) {
            const float* W  = L ? (ew2 + i * 16384) : (ew1 + i * 16384);
            const float* bb = L ? (eb2 + i * 128)   : (eb1 + i * 128);
            k_bias<<<1, 128>>>(bb, kv);
            gemm<128><<<GG, 256>>>(W, 0, NN);
            k_point<<<WG, 256>>>(kv);
            k_aggexp<<<WG, 256>>>(kv);
        }
        k_logmap<<<WG, 256>>>(kv);
        k_pool<<<BB, 128>>>(0, i * 128, batch);
    }

    // gate path
    k_gate1<<<(NN + 31) / 32, 256>>>(x, gw1);
    k_gagg1<<<WG, 256>>>(gb1);
    gemm<32><<<GG, 256>>>(gw2, 1, NN);
    k_gagg2<<<WG, 256>>>(gb2);
    k_pool<<<BB, 128>>>(1, 0, batch);

    k_finalize<<<BB, 128>>>(gu, traw, out, out_size, batch);
}